// round 4
// baseline (speedup 1.0000x reference)
#include <cuda_runtime.h>

// TransOp expm: out[b, s*8..] = expm(A_{b,s}) @ x[b, s*8..]
// A_{b,s} = sum_m c[b,m] * psi[m,s,:,:]   (8x8), one thread per (b,s).
//
// Method: Taylor-action (Al-Mohy/Higham style). Warp-uniform (order m, reps r)
// chosen from warp-max ||A||_inf:
//   wmax <= 3.2 : m=16, r=1   (err ~ 3.2^17/17! ~ 1.1e-6)
//   wmax <= 6.0 : m=24, r=1   (err ~ 6^25/25!   ~ 1.8e-6)
//   else        : m=16, r=ceil(wmax/3.2)
// Horner: v = b; for j=m..1: v = b + (A v)/j; repeated r times on A/r.
//
// All heavy FP uses packed f32x2 (FFMA2): A held as 32 x 64-bit regs, each
// packing the same column k of adjacent rows {2n2, 2n2+1}. psi is staged in
// shared memory already in this row-paired layout so the packed A-build reads
// 64-bit smem words directly.

typedef unsigned long long ull;

#define BDIM 256

__constant__ float INV_TAB[32] = {
    0.0f,      1.0f,      1.0f/2,    1.0f/3,    1.0f/4,    1.0f/5,
    1.0f/6,    1.0f/7,    1.0f/8,    1.0f/9,    1.0f/10,   1.0f/11,
    1.0f/12,   1.0f/13,   1.0f/14,   1.0f/15,   1.0f/16,   1.0f/17,
    1.0f/18,   1.0f/19,   1.0f/20,   1.0f/21,   1.0f/22,   1.0f/23,
    1.0f/24,   1.0f/25,   1.0f/26,   1.0f/27,   1.0f/28,   1.0f/29,
    1.0f/30,   1.0f/31
};

__device__ __forceinline__ ull dup2(float v) {
    ull r; asm("mov.b64 %0, {%1,%1};" : "=l"(r) : "f"(v)); return r;
}
__device__ __forceinline__ void unpack2(ull v, float& lo, float& hi) {
    asm("mov.b64 {%0,%1}, %2;" : "=f"(lo), "=f"(hi) : "l"(v));
}
__device__ __forceinline__ ull fma2(ull a, ull b, ull c) {
    ull d; asm("fma.rn.f32x2 %0, %1, %2, %3;" : "=l"(d) : "l"(a), "l"(b), "l"(c)); return d;
}
__device__ __forceinline__ ull mul2(ull a, ull b) {
    ull d; asm("mul.rn.f32x2 %0, %1, %2;" : "=l"(d) : "l"(a), "l"(b)); return d;
}
__device__ __forceinline__ ull add2(ull a, ull b) {
    ull d; asm("add.rn.f32x2 %0, %1, %2;" : "=l"(d) : "l"(a), "l"(b)); return d;
}

__global__ __launch_bounds__(BDIM) void transop_expm_kernel(
    const float* __restrict__ x,
    const float* __restrict__ c,
    const float* __restrict__ psi,
    float* __restrict__ out)
{
    // psi slice for this CTA's s, row-paired packed:
    // ps2[m][n2*8+k] = { psi[m,s,2*n2,k], psi[m,s,2*n2+1,k] }
    __shared__ ull ps2[16][32];

    const int s = blockIdx.x & 63;
    const int b = (blockIdx.x >> 6) * BDIM + threadIdx.x;

    // Stage psi: 256 threads x one float4 each (1024 floats total).
    {
        const int t = threadIdx.x;
        const int m = t >> 4;            // 0..15
        const int j = (t & 15) << 2;     // 0,4,...,60 : linear n*8+k
        const float4 v = *reinterpret_cast<const float4*>(psi + ((m * 64 + s) << 6) + j);
        const int n = j >> 3;            // row 0..7
        const int k0 = j & 7;            // 0 or 4
        float* dst = reinterpret_cast<float*>(&ps2[m][(n >> 1) * 8 + k0]);
        const int w = n & 1;             // lo/hi half of the pair
        dst[0 * 2 + w] = v.x;
        dst[1 * 2 + w] = v.y;
        dst[2 * 2 + w] = v.z;
        dst[3 * 2 + w] = v.w;
    }
    __syncthreads();

    // c[b, 0..15], duplicated into packed form.
    ull cm2[16];
    {
        const float4* cb = reinterpret_cast<const float4*>(c + b * 16);
#pragma unroll
        for (int q = 0; q < 4; ++q) {
            const float4 cv = cb[q];
            cm2[q * 4 + 0] = dup2(cv.x);
            cm2[q * 4 + 1] = dup2(cv.y);
            cm2[q * 4 + 2] = dup2(cv.z);
            cm2[q * 4 + 3] = dup2(cv.w);
        }
    }

    // Packed A build: A2[n2*8+k] = { A[2n2][k], A[2n2+1][k] }
    ull A2[32];
#pragma unroll
    for (int i = 0; i < 32; ++i) A2[i] = mul2(cm2[0], ps2[0][i]);
#pragma unroll
    for (int m = 1; m < 16; ++m) {
#pragma unroll
        for (int i = 0; i < 32; ++i) A2[i] = fma2(cm2[m], ps2[m][i], A2[i]);
    }

    // Infinity norm: packed abs-rowsum gives both rows of a pair at once.
    float ninf = 0.0f;
    {
        const ull mask = 0x7FFFFFFF7FFFFFFFULL;
#pragma unroll
        for (int n2 = 0; n2 < 4; ++n2) {
            ull acc = A2[n2 * 8] & mask;
#pragma unroll
            for (int k = 1; k < 8; ++k) acc = add2(acc, A2[n2 * 8 + k] & mask);
            float r0, r1; unpack2(acc, r0, r1);
            ninf = fmaxf(ninf, fmaxf(r0, r1));
        }
    }

    // Warp-uniform (order, reps) selection from warp-max norm.
    const float wmax = __uint_as_float(
        __reduce_max_sync(0xffffffffu, __float_as_uint(ninf)));

    int m_ord, r;
    if (wmax <= 3.2f)       { m_ord = 16; r = 1; }
    else if (wmax <= 6.0f)  { m_ord = 24; r = 1; }
    else {
        r = (int)ceilf(wmax * (1.0f / 3.2f));
        if (r > 31) r = 31;
        m_ord = 16;
    }

    // Scale A by 1/r (exact 1.0 when r==1).
    {
        const ull s2 = dup2(INV_TAB[r] + (r == 1 ? 0.0f : 0.0f));
#pragma unroll
        for (int i = 0; i < 32; ++i) A2[i] = mul2(A2[i], s2);
    }

    // Load x block (pairs are naturally adjacent floats).
    ull v2[4];
    {
        const ull* xb = reinterpret_cast<const ull*>(x + b * 512 + s * 8);
        v2[0] = xb[0]; v2[1] = xb[1]; v2[2] = xb[2]; v2[3] = xb[3];
    }

    // r repetitions of order-m Horner Taylor action.
    for (int rr = 0; rr < r; ++rr) {
        ull b2[4];
#pragma unroll
        for (int i = 0; i < 4; ++i) b2[i] = v2[i];

        for (int j = m_ord; j > 0; --j) {
            float vf[8];
            unpack2(v2[0], vf[0], vf[1]);
            unpack2(v2[1], vf[2], vf[3]);
            unpack2(v2[2], vf[4], vf[5]);
            unpack2(v2[3], vf[6], vf[7]);
            ull d[8];
#pragma unroll
            for (int k = 0; k < 8; ++k) d[k] = dup2(vf[k]);

            ull w2[4];
#pragma unroll
            for (int n2 = 0; n2 < 4; ++n2) {
                ull acc = mul2(A2[n2 * 8], d[0]);
#pragma unroll
                for (int k = 1; k < 8; ++k) acc = fma2(A2[n2 * 8 + k], d[k], acc);
                w2[n2] = acc;
            }

            const ull s2 = dup2(INV_TAB[j]);
#pragma unroll
            for (int n2 = 0; n2 < 4; ++n2) v2[n2] = fma2(w2[n2], s2, b2[n2]);
        }
    }

    // Store (packed pairs are already in output element order).
    {
        ull* ob = reinterpret_cast<ull*>(out + b * 512 + s * 8);
        ob[0] = v2[0]; ob[1] = v2[1]; ob[2] = v2[2]; ob[3] = v2[3];
    }
}

extern "C" void kernel_launch(void* const* d_in, const int* in_sizes, int n_in,
                              void* d_out, int out_size)
{
    const float* x   = (const float*)d_in[0];   // (B, 512)
    const float* c   = (const float*)d_in[1];   // (B, 16)
    const float* psi = (const float*)d_in[2];   // (16, 64, 8, 8)
    float* out = (float*)d_out;                 // (B, 512)

    const int B = in_sizes[0] / 512;            // 8192
    const dim3 grid((B / BDIM) * 64);           // 2048 CTAs: fixed s, 256 b's each
    transop_expm_kernel<<<grid, BDIM>>>(x, c, psi, out);
}

// round 5
// speedup vs baseline: 1.0033x; 1.0033x over previous
#include <cuda_runtime.h>

// TransOp expm: out[b, s*8..] = expm(A_{b,s}) @ x[b, s*8..]
// A_{b,s} = sum_m c[b,m] * psi[m,s,:,:]   (8x8), one thread per (b,s).
//
// Method: Taylor-action (Al-Mohy/Higham style). Warp-uniform (order m, reps r)
// chosen from warp-max ||A||_inf:
//   wmax <= 3.2 : m=16, r=1   (err ~ 3.2^17/17! ~ 1.1e-6)
//   wmax <= 6.0 : m=24, r=1   (err ~ 6^25/25!   ~ 1.8e-6)
//   else        : m=16, r=ceil(wmax/3.2)
// Horner: v = b; for j=m..1: v = b + (A v)/j; repeated r times on A/r.
//
// All heavy FP uses packed f32x2 (FFMA2): A held as 32 x 64-bit regs, each
// packing the same column k of adjacent rows {2n2, 2n2+1}. psi is staged in
// shared memory already in this row-paired layout so the packed A-build reads
// 64-bit smem words directly.

typedef unsigned long long ull;

#define BDIM 256

__constant__ float INV_TAB[32] = {
    0.0f,      1.0f,      1.0f/2,    1.0f/3,    1.0f/4,    1.0f/5,
    1.0f/6,    1.0f/7,    1.0f/8,    1.0f/9,    1.0f/10,   1.0f/11,
    1.0f/12,   1.0f/13,   1.0f/14,   1.0f/15,   1.0f/16,   1.0f/17,
    1.0f/18,   1.0f/19,   1.0f/20,   1.0f/21,   1.0f/22,   1.0f/23,
    1.0f/24,   1.0f/25,   1.0f/26,   1.0f/27,   1.0f/28,   1.0f/29,
    1.0f/30,   1.0f/31
};

__device__ __forceinline__ ull dup2(float v) {
    ull r; asm("mov.b64 %0, {%1,%1};" : "=l"(r) : "f"(v)); return r;
}
__device__ __forceinline__ void unpack2(ull v, float& lo, float& hi) {
    asm("mov.b64 {%0,%1}, %2;" : "=f"(lo), "=f"(hi) : "l"(v));
}
__device__ __forceinline__ ull fma2(ull a, ull b, ull c) {
    ull d; asm("fma.rn.f32x2 %0, %1, %2, %3;" : "=l"(d) : "l"(a), "l"(b), "l"(c)); return d;
}
__device__ __forceinline__ ull mul2(ull a, ull b) {
    ull d; asm("mul.rn.f32x2 %0, %1, %2;" : "=l"(d) : "l"(a), "l"(b)); return d;
}
__device__ __forceinline__ ull add2(ull a, ull b) {
    ull d; asm("add.rn.f32x2 %0, %1, %2;" : "=l"(d) : "l"(a), "l"(b)); return d;
}

__global__ __launch_bounds__(BDIM) void transop_expm_kernel(
    const float* __restrict__ x,
    const float* __restrict__ c,
    const float* __restrict__ psi,
    float* __restrict__ out)
{
    // psi slice for this CTA's s, row-paired packed:
    // ps2[m][n2*8+k] = { psi[m,s,2*n2,k], psi[m,s,2*n2+1,k] }
    __shared__ ull ps2[16][32];

    const int s = blockIdx.x & 63;
    const int b = (blockIdx.x >> 6) * BDIM + threadIdx.x;

    // Stage psi: 256 threads x one float4 each (1024 floats total).
    {
        const int t = threadIdx.x;
        const int m = t >> 4;            // 0..15
        const int j = (t & 15) << 2;     // 0,4,...,60 : linear n*8+k
        const float4 v = *reinterpret_cast<const float4*>(psi + ((m * 64 + s) << 6) + j);
        const int n = j >> 3;            // row 0..7
        const int k0 = j & 7;            // 0 or 4
        float* dst = reinterpret_cast<float*>(&ps2[m][(n >> 1) * 8 + k0]);
        const int w = n & 1;             // lo/hi half of the pair
        dst[0 * 2 + w] = v.x;
        dst[1 * 2 + w] = v.y;
        dst[2 * 2 + w] = v.z;
        dst[3 * 2 + w] = v.w;
    }
    __syncthreads();

    // c[b, 0..15], duplicated into packed form.
    ull cm2[16];
    {
        const float4* cb = reinterpret_cast<const float4*>(c + b * 16);
#pragma unroll
        for (int q = 0; q < 4; ++q) {
            const float4 cv = cb[q];
            cm2[q * 4 + 0] = dup2(cv.x);
            cm2[q * 4 + 1] = dup2(cv.y);
            cm2[q * 4 + 2] = dup2(cv.z);
            cm2[q * 4 + 3] = dup2(cv.w);
        }
    }

    // Packed A build: A2[n2*8+k] = { A[2n2][k], A[2n2+1][k] }
    ull A2[32];
#pragma unroll
    for (int i = 0; i < 32; ++i) A2[i] = mul2(cm2[0], ps2[0][i]);
#pragma unroll
    for (int m = 1; m < 16; ++m) {
#pragma unroll
        for (int i = 0; i < 32; ++i) A2[i] = fma2(cm2[m], ps2[m][i], A2[i]);
    }

    // Infinity norm: packed abs-rowsum gives both rows of a pair at once.
    float ninf = 0.0f;
    {
        const ull mask = 0x7FFFFFFF7FFFFFFFULL;
#pragma unroll
        for (int n2 = 0; n2 < 4; ++n2) {
            ull acc = A2[n2 * 8] & mask;
#pragma unroll
            for (int k = 1; k < 8; ++k) acc = add2(acc, A2[n2 * 8 + k] & mask);
            float r0, r1; unpack2(acc, r0, r1);
            ninf = fmaxf(ninf, fmaxf(r0, r1));
        }
    }

    // Warp-uniform (order, reps) selection from warp-max norm.
    const float wmax = __uint_as_float(
        __reduce_max_sync(0xffffffffu, __float_as_uint(ninf)));

    int m_ord, r;
    if (wmax <= 3.2f)       { m_ord = 16; r = 1; }
    else if (wmax <= 6.0f)  { m_ord = 24; r = 1; }
    else {
        r = (int)ceilf(wmax * (1.0f / 3.2f));
        if (r > 31) r = 31;
        m_ord = 16;
    }

    // Scale A by 1/r (exact 1.0 when r==1).
    {
        const ull s2 = dup2(INV_TAB[r] + (r == 1 ? 0.0f : 0.0f));
#pragma unroll
        for (int i = 0; i < 32; ++i) A2[i] = mul2(A2[i], s2);
    }

    // Load x block (pairs are naturally adjacent floats).
    ull v2[4];
    {
        const ull* xb = reinterpret_cast<const ull*>(x + b * 512 + s * 8);
        v2[0] = xb[0]; v2[1] = xb[1]; v2[2] = xb[2]; v2[3] = xb[3];
    }

    // r repetitions of order-m Horner Taylor action.
    for (int rr = 0; rr < r; ++rr) {
        ull b2[4];
#pragma unroll
        for (int i = 0; i < 4; ++i) b2[i] = v2[i];

        for (int j = m_ord; j > 0; --j) {
            float vf[8];
            unpack2(v2[0], vf[0], vf[1]);
            unpack2(v2[1], vf[2], vf[3]);
            unpack2(v2[2], vf[4], vf[5]);
            unpack2(v2[3], vf[6], vf[7]);
            ull d[8];
#pragma unroll
            for (int k = 0; k < 8; ++k) d[k] = dup2(vf[k]);

            ull w2[4];
#pragma unroll
            for (int n2 = 0; n2 < 4; ++n2) {
                ull acc = mul2(A2[n2 * 8], d[0]);
#pragma unroll
                for (int k = 1; k < 8; ++k) acc = fma2(A2[n2 * 8 + k], d[k], acc);
                w2[n2] = acc;
            }

            const ull s2 = dup2(INV_TAB[j]);
#pragma unroll
            for (int n2 = 0; n2 < 4; ++n2) v2[n2] = fma2(w2[n2], s2, b2[n2]);
        }
    }

    // Store (packed pairs are already in output element order).
    {
        ull* ob = reinterpret_cast<ull*>(out + b * 512 + s * 8);
        ob[0] = v2[0]; ob[1] = v2[1]; ob[2] = v2[2]; ob[3] = v2[3];
    }
}

extern "C" void kernel_launch(void* const* d_in, const int* in_sizes, int n_in,
                              void* d_out, int out_size)
{
    const float* x   = (const float*)d_in[0];   // (B, 512)
    const float* c   = (const float*)d_in[1];   // (B, 16)
    const float* psi = (const float*)d_in[2];   // (16, 64, 8, 8)
    float* out = (float*)d_out;                 // (B, 512)

    const int B = in_sizes[0] / 512;            // 8192
    const dim3 grid((B / BDIM) * 64);           // 2048 CTAs: fixed s, 256 b's each
    transop_expm_kernel<<<grid, BDIM>>>(x, c, psi, out);
}

// round 6
// speedup vs baseline: 1.1078x; 1.1042x over previous
#include <cuda_runtime.h>

// TransOp expm: out[b, s*8..] = expm(A_{b,s}) @ x[b, s*8..]
// A_{b,s} = sum_m c[b,m] * psi[m,s,:,:]  (8x8).
//
// TWO threads per (b,s): thread h in {0,1} owns rows 4h..4h+3 (two packed
// row-pairs) of A. Columns are stored permuted per thread (k = c' ^ 4h) so
// that multiplier slots 0..3 are always the thread's OWN output elements and
// slots 4..7 are the partner's, exchanged with 4 shfl.xor per Horner step.
//
// Taylor action, warp-uniform (order m, reps r) from warp-max ||A||_inf:
//   wmax<=3.2: m=14   wmax<=4.6: m=17   wmax<=6.0: m=20
//   else: r=ceil(wmax/3.2), m=14, A scaled by 1/r.
// Horner: v = b; for j=m..1: v = b + (A v)/j.
//
// All heavy FP is packed f32x2 (FFMA2).

typedef unsigned long long ull;

#define BDIM 256

__constant__ float INV_TAB[32] = {
    0.0f,    1.0f,    1.0f/2,  1.0f/3,  1.0f/4,  1.0f/5,
    1.0f/6,  1.0f/7,  1.0f/8,  1.0f/9,  1.0f/10, 1.0f/11,
    1.0f/12, 1.0f/13, 1.0f/14, 1.0f/15, 1.0f/16, 1.0f/17,
    1.0f/18, 1.0f/19, 1.0f/20, 1.0f/21, 1.0f/22, 1.0f/23,
    1.0f/24, 1.0f/25, 1.0f/26, 1.0f/27, 1.0f/28, 1.0f/29,
    1.0f/30, 1.0f/31
};

__device__ __forceinline__ ull dup2(float v) {
    ull r; asm("mov.b64 %0, {%1,%1};" : "=l"(r) : "f"(v)); return r;
}
__device__ __forceinline__ void unpack2(ull v, float& lo, float& hi) {
    asm("mov.b64 {%0,%1}, %2;" : "=f"(lo), "=f"(hi) : "l"(v));
}
__device__ __forceinline__ ull fma2(ull a, ull b, ull c) {
    ull d; asm("fma.rn.f32x2 %0, %1, %2, %3;" : "=l"(d) : "l"(a), "l"(b), "l"(c)); return d;
}
__device__ __forceinline__ ull mul2(ull a, ull b) {
    ull d; asm("mul.rn.f32x2 %0, %1, %2;" : "=l"(d) : "l"(a), "l"(b)); return d;
}
__device__ __forceinline__ ull add2(ull a, ull b) {
    ull d; asm("add.rn.f32x2 %0, %1, %2;" : "=l"(d) : "l"(a), "l"(b)); return d;
}

__global__ __launch_bounds__(BDIM, 3) void transop_expm_kernel(
    const float* __restrict__ x,
    const float* __restrict__ c,
    const float* __restrict__ psi,
    float* __restrict__ out)
{
    // psi slice for this CTA's s, row-paired packed:
    // ps2[m][n2*8+k] = { psi[m,s,2*n2,k], psi[m,s,2*n2+1,k] }
    __shared__ ull ps2[16][32];

    const int s = blockIdx.x & 63;
    const int t = threadIdx.x;
    const int h = t & 1;                              // row-half owner
    const int b = (blockIdx.x >> 6) * (BDIM / 2) + (t >> 1);

    // Stage psi: 256 threads x one float4 each (1024 floats total).
    {
        const int m = t >> 4;            // 0..15
        const int j = (t & 15) << 2;     // 0,4,...,60 : linear n*8+k
        const float4 v = *reinterpret_cast<const float4*>(psi + ((m * 64 + s) << 6) + j);
        const int n = j >> 3;            // row 0..7
        const int k0 = j & 7;            // 0 or 4
        float* dst = reinterpret_cast<float*>(&ps2[m][(n >> 1) * 8 + k0]);
        const int w = n & 1;             // lo/hi half of the pair
        dst[0 * 2 + w] = v.x;
        dst[1 * 2 + w] = v.y;
        dst[2 * 2 + w] = v.z;
        dst[3 * 2 + w] = v.w;
    }
    __syncthreads();

    // c[b, 0..15] as scalars (dup'd per-m inside the build loop).
    float cm[16];
    {
        const float4* cb = reinterpret_cast<const float4*>(c + b * 16);
#pragma unroll
        for (int q = 0; q < 4; ++q) {
            const float4 cv = cb[q];
            cm[q * 4 + 0] = cv.x; cm[q * 4 + 1] = cv.y;
            cm[q * 4 + 2] = cv.z; cm[q * 4 + 3] = cv.w;
        }
    }

    // Packed A build for this thread's two row-pairs (rows 4h..4h+3), with
    // columns permuted: A2[p*8 + c'] = column k = c' ^ (4h).
    // c' in 0..3 -> k = 4h + c'   (own slots)
    // c' in 4..7 -> k = 4(1-h) + (c'-4)  (partner slots)
    const int r0 = (2 * h + 0) * 8;      // smem row offset, local pair 0
    const int r1 = (2 * h + 1) * 8;      // local pair 1
    const int ca = 4 * h;                // own-column base
    const int cb_ = 4 - 4 * h;           // partner-column base

    ull A2[16];
#pragma unroll
    for (int m = 0; m < 16; ++m) {
        const ull cd = dup2(cm[m]);
        if (m == 0) {
#pragma unroll
            for (int q = 0; q < 4; ++q) {
                A2[0  + q] = mul2(cd, ps2[0][r0 + ca  + q]);
                A2[4  + q] = mul2(cd, ps2[0][r0 + cb_ + q]);
                A2[8  + q] = mul2(cd, ps2[0][r1 + ca  + q]);
                A2[12 + q] = mul2(cd, ps2[0][r1 + cb_ + q]);
            }
        } else {
#pragma unroll
            for (int q = 0; q < 4; ++q) {
                A2[0  + q] = fma2(cd, ps2[m][r0 + ca  + q], A2[0  + q]);
                A2[4  + q] = fma2(cd, ps2[m][r0 + cb_ + q], A2[4  + q]);
                A2[8  + q] = fma2(cd, ps2[m][r1 + ca  + q], A2[8  + q]);
                A2[12 + q] = fma2(cd, ps2[m][r1 + cb_ + q], A2[12 + q]);
            }
        }
    }

    // Partial infinity norm over this thread's 4 rows (permutation is
    // irrelevant to row sums). Warp reduce covers the partner too.
    float ninf = 0.0f;
    {
        const ull mask = 0x7FFFFFFF7FFFFFFFULL;
#pragma unroll
        for (int p = 0; p < 2; ++p) {
            ull acc = A2[p * 8] & mask;
#pragma unroll
            for (int k = 1; k < 8; ++k) acc = add2(acc, A2[p * 8 + k] & mask);
            float a0, a1; unpack2(acc, a0, a1);
            ninf = fmaxf(ninf, fmaxf(a0, a1));
        }
    }
    const float wmax = __uint_as_float(
        __reduce_max_sync(0xffffffffu, __float_as_uint(ninf)));

    int m_ord, r;
    if (wmax <= 3.2f)       { m_ord = 14; r = 1; }
    else if (wmax <= 4.6f)  { m_ord = 17; r = 1; }
    else if (wmax <= 6.0f)  { m_ord = 20; r = 1; }
    else {
        r = (int)ceilf(wmax * (1.0f / 3.2f));
        if (r > 31) r = 31;
        m_ord = 14;
    }

    // Scale A by 1/r (exact 1.0 when r==1).
    {
        const ull s2 = dup2(INV_TAB[r]);
#pragma unroll
        for (int i = 0; i < 16; ++i) A2[i] = mul2(A2[i], s2);
    }

    // Own 4 elements of the x block: rows 4h..4h+3 (two packed pairs).
    ull v0, v1;
    {
        const ull* xb = reinterpret_cast<const ull*>(x + b * 512 + s * 8 + 4 * h);
        v0 = xb[0]; v1 = xb[1];
    }

    // r repetitions of order-m Horner Taylor action.
    for (int rr = 0; rr < r; ++rr) {
        const ull b0 = v0, b1 = v1;
        for (int j = m_ord; j > 0; --j) {
            // Own multipliers (slots 0..3) straight from v; partner's
            // (slots 4..7) via shfl.xor with the adjacent lane.
            float o0, o1, o2, o3;
            unpack2(v0, o0, o1);
            unpack2(v1, o2, o3);
            const float q0 = __shfl_xor_sync(0xffffffffu, o0, 1);
            const float q1 = __shfl_xor_sync(0xffffffffu, o1, 1);
            const float q2 = __shfl_xor_sync(0xffffffffu, o2, 1);
            const float q3 = __shfl_xor_sync(0xffffffffu, o3, 1);

            const ull d0 = dup2(o0), d1 = dup2(o1), d2 = dup2(o2), d3 = dup2(o3);
            const ull d4 = dup2(q0), d5 = dup2(q1), d6 = dup2(q2), d7 = dup2(q3);

            ull w0 = mul2(A2[0], d0);
            w0 = fma2(A2[1], d1, w0);
            w0 = fma2(A2[2], d2, w0);
            w0 = fma2(A2[3], d3, w0);
            w0 = fma2(A2[4], d4, w0);
            w0 = fma2(A2[5], d5, w0);
            w0 = fma2(A2[6], d6, w0);
            w0 = fma2(A2[7], d7, w0);

            ull w1 = mul2(A2[8], d0);
            w1 = fma2(A2[9],  d1, w1);
            w1 = fma2(A2[10], d2, w1);
            w1 = fma2(A2[11], d3, w1);
            w1 = fma2(A2[12], d4, w1);
            w1 = fma2(A2[13], d5, w1);
            w1 = fma2(A2[14], d6, w1);
            w1 = fma2(A2[15], d7, w1);

            const ull sj = dup2(INV_TAB[j]);
            v0 = fma2(w0, sj, b0);
            v1 = fma2(w1, sj, b1);
        }
    }

    // Store own 4 output elements (16B, consecutive per thread pair).
    {
        ull* ob = reinterpret_cast<ull*>(out + b * 512 + s * 8 + 4 * h);
        ob[0] = v0; ob[1] = v1;
    }
}

extern "C" void kernel_launch(void* const* d_in, const int* in_sizes, int n_in,
                              void* d_out, int out_size)
{
    const float* x   = (const float*)d_in[0];   // (B, 512)
    const float* c   = (const float*)d_in[1];   // (B, 16)
    const float* psi = (const float*)d_in[2];   // (16, 64, 8, 8)
    float* out = (float*)d_out;                 // (B, 512)

    const int B = in_sizes[0] / 512;            // 8192
    // 2 threads per (b,s): each CTA covers one s and BDIM/2 = 128 b's.
    const dim3 grid((B / (BDIM / 2)) * 64);     // 4096 CTAs
    transop_expm_kernel<<<grid, BDIM>>>(x, c, psi, out);
}